// round 10
// baseline (speedup 1.0000x reference)
#include <cuda_runtime.h>
#include <cuda_bf16.h>
#include <cstdint>
#include <math.h>
#include <float.h>

// ---------------- problem constants ----------------
#define NBATCH 8
#define TT 512
#define DIM 1024
#define NS 2048
#define NH 4
#define NKTOP 8
#define NDh 256
#define NG 128            // persistent CTAs in scan kernel
#define LR_FAST 1.0f
#define LR_DEEP 0.1f
#define SURPRISE_TH 0.6f
#define DECAYF 0.9995f
#define INV_SQRT_DH 0.0625f    // 1/sqrt(256)
#define INV_SQRT_D  0.03125f   // 1/sqrt(1024)

// scan smem layout (floats)
#define SM_KS 0              // 16*1024
#define SM_WF 16384          // 1024*8 (v-part of fuse_W only)
#define SM_XC 24576          // 8*2048 (concat h_t | v_t)
#define SM_RED 40960         // 64 floats (topk lists; red[40..55] LN stats)
#define SM_REDI 41024        // 64 ints
#define SM_LNG 41088         // 1024
#define SM_LNB 42112         // 1024
#define SMEM_FLOATS 43136
#define SMEM_BYTES (SMEM_FLOATS * 4)   // 172544

// gemm tiling
#define BM 128
#define BN 128
#define BK 32
#define PCH 10240            // piece stride bytes: 128 rows * 40 bf16 * 2B
#define BUFSZ (4 * PCH)      // Ahi|Alo|Bhi|Blo
#define GEMM_SMEM_BYTES (2 * BUFSZ)   // 81920

#define SCO (NBATCH * NH * NS)
#define SWO (NBATCH * NS)

// ---------------- scratch globals (no runtime alloc) ----------------
__device__ float g_h[NBATCH * TT * DIM];
__device__ float g_y[NBATCH * TT * DIM];        // backbone mlp out; later fused_h
__device__ float g_Vbuf[NS * DIM];
__device__ float g_scores[2 * SCO];
__device__ float g_sw[2 * SWO];
__device__ float g_vt[2 * NBATCH * DIM];
__device__ float g_fusedraw[2 * NBATCH * DIM];
__device__ int   g_slot[2][NBATCH];
__device__ float g_lr[2][NBATCH];
__device__ float g_cpre[TT];
__device__ float g_cpost[TT];
__device__ int g_mask_kind;
// epoch flags (monotonic within one launch; init_kernel zeroes them)
__device__ int g_fscore[NG];
__device__ int g_fvt[64];
__device__ int g_ffused[NG];
// bf16 hi/lo split buffers
__device__ __align__(16) __nv_bfloat16 g_hhi[NBATCH * TT * DIM];
__device__ __align__(16) __nv_bfloat16 g_hlo[NBATCH * TT * DIM];
__device__ __align__(16) __nv_bfloat16 g_thi[NBATCH * TT * 2 * DIM];
__device__ __align__(16) __nv_bfloat16 g_tlo[NBATCH * TT * 2 * DIM];
__device__ __align__(16) __nv_bfloat16 g_w1thi[2 * DIM * DIM];   // [2048][1024]
__device__ __align__(16) __nv_bfloat16 g_w1tlo[2 * DIM * DIM];
__device__ __align__(16) __nv_bfloat16 g_w2thi[2 * DIM * DIM];   // [1024][2048]
__device__ __align__(16) __nv_bfloat16 g_w2tlo[2 * DIM * DIM];

// ---------------- PTX helpers (base PTX only: valid at target sm_103) ----------------
__device__ __forceinline__ uint32_t smem_u32(const void* p) {
    uint32_t a;
    asm("{ .reg .u64 t; cvta.to.shared.u64 t, %1; cvt.u32.u64 %0, t; }"
        : "=r"(a) : "l"(p));
    return a;
}
__device__ __forceinline__ void cp_async16(uint32_t saddr, const void* gaddr) {
    asm volatile("cp.async.cg.shared.global [%0], [%1], 16;" :: "r"(saddr), "l"(gaddr));
}
__device__ __forceinline__ void cp_commit() {
    asm volatile("cp.async.commit_group;" ::: "memory");
}
__device__ __forceinline__ void cp_wait_all() {
    asm volatile("cp.async.wait_group 0;" ::: "memory");
}
__device__ __forceinline__ void ldmatrix_x4(uint32_t* r, uint32_t addr) {
    asm volatile("ldmatrix.sync.aligned.m8n8.x4.shared.b16 {%0,%1,%2,%3}, [%4];"
        : "=r"(r[0]), "=r"(r[1]), "=r"(r[2]), "=r"(r[3]) : "r"(addr));
}
__device__ __forceinline__ void ldmatrix_x2(uint32_t* r, uint32_t addr) {
    asm volatile("ldmatrix.sync.aligned.m8n8.x2.shared.b16 {%0,%1}, [%2];"
        : "=r"(r[0]), "=r"(r[1]) : "r"(addr));
}
__device__ __forceinline__ void mma16816(float* c, const uint32_t* a, const uint32_t* b) {
    asm volatile("mma.sync.aligned.m16n8k16.row.col.f32.bf16.bf16.f32 "
        "{%0,%1,%2,%3}, {%4,%5,%6,%7}, {%8,%9}, {%0,%1,%2,%3};"
        : "+f"(c[0]), "+f"(c[1]), "+f"(c[2]), "+f"(c[3])
        : "r"(a[0]), "r"(a[1]), "r"(a[2]), "r"(a[3]), "r"(b[0]), "r"(b[1]));
}
__device__ __forceinline__ void st_rel(int* p, int v) {
    asm volatile("st.release.gpu.global.s32 [%0], %1;" :: "l"(p), "r"(v) : "memory");
}
__device__ __forceinline__ int ld_acq(const int* p) {
    int v;
    asm volatile("ld.acquire.gpu.global.s32 %0, [%1];" : "=r"(v) : "l"(p) : "memory");
    return v;
}
__device__ __forceinline__ void wait_n(const int* flags, int n, int tgt, int tid) {
    for (;;) {
        int v = (tid < n) ? ld_acq(flags + tid) : tgt;
        if (__syncthreads_and(v >= tgt)) break;
    }
}

// ---------------- small math helpers ----------------
__device__ __forceinline__ float gelu_tanh(float x) {
    const float c = 0.7978845608028654f;
    float t = tanhf(c * (x + 0.044715f * x * x * x));
    return 0.5f * x * (1.0f + t);
}
__device__ __forceinline__ float blockSum256(float v, float* red, int tid) {
    #pragma unroll
    for (int o = 16; o; o >>= 1) v += __shfl_xor_sync(0xFFFFFFFFu, v, o);
    if ((tid & 31) == 0) red[tid >> 5] = v;
    __syncthreads();
    if (tid < 32) {
        float x = (tid < 8) ? red[tid] : 0.0f;
        #pragma unroll
        for (int o = 4; o; o >>= 1) x += __shfl_xor_sync(0xFFFFFFFFu, x, o);
        if (tid == 0) red[32] = x;
    }
    __syncthreads();
    float r = red[32];
    __syncthreads();
    return r;
}
__device__ __forceinline__ void blockArgMax256(float v, int i, float* red, int* redi,
                                               int tid, float& mv, int& mi) {
    #pragma unroll
    for (int o = 16; o; o >>= 1) {
        float v2 = __shfl_xor_sync(0xFFFFFFFFu, v, o);
        int   i2 = __shfl_xor_sync(0xFFFFFFFFu, i, o);
        if (v2 > v || (v2 == v && i2 < i)) { v = v2; i = i2; }
    }
    if ((tid & 31) == 0) { red[tid >> 5] = v; redi[tid >> 5] = i; }
    __syncthreads();
    if (tid == 0) {
        for (int k = 1; k < 8; k++) {
            if (red[k] > v || (red[k] == v && redi[k] < i)) { v = red[k]; i = redi[k]; }
        }
        red[32] = v; redi[32] = i;
    }
    __syncthreads();
    mv = red[32]; mi = redi[32];
    __syncthreads();
}

// ---------------- top-8 merge machinery (total order: value desc, index asc) ----
__device__ __forceinline__ bool kv_gt(float av, int ai, float bv, int bi) {
    return av > bv || (av == bv && ai < bi);
}
#define KV_CE(x, y) { \
    if (!kv_gt(v[x], ii[x], v[y], ii[y])) { \
        float tv = v[x]; v[x] = v[y]; v[y] = tv; \
        int ti = ii[x]; ii[x] = ii[y]; ii[y] = ti; } }

__device__ __forceinline__ void kv_sort8(float* v, int* ii) {
    KV_CE(0,1) KV_CE(2,3) KV_CE(4,5) KV_CE(6,7)
    KV_CE(0,2) KV_CE(1,3) KV_CE(4,6) KV_CE(5,7)
    KV_CE(1,2) KV_CE(5,6)
    KV_CE(0,4) KV_CE(1,5) KV_CE(2,6) KV_CE(3,7)
    KV_CE(2,4) KV_CE(3,5)
    KV_CE(1,2) KV_CE(3,4) KV_CE(5,6)
}
__device__ __forceinline__ void kv_merge8(float* v, int* ii, const float* pv, const int* pi) {
    #pragma unroll
    for (int e = 0; e < 8; e++) {
        if (!kv_gt(v[e], ii[e], pv[7 - e], pi[7 - e])) {
            v[e] = pv[7 - e]; ii[e] = pi[7 - e];
        }
    }
    KV_CE(0,4) KV_CE(1,5) KV_CE(2,6) KV_CE(3,7)
    KV_CE(0,2) KV_CE(1,3) KV_CE(4,6) KV_CE(5,7)
    KV_CE(0,1) KV_CE(2,3) KV_CE(4,5) KV_CE(6,7)
}
__device__ __forceinline__ void kv_bfly(float* v, int* ii, int off) {
    float pv[8]; int pi[8];
    #pragma unroll
    for (int e = 0; e < 8; e++) {
        pv[e] = __shfl_xor_sync(0xFFFFFFFFu, v[e], off);
        pi[e] = __shfl_xor_sync(0xFFFFFFFFu, ii[e], off);
    }
    kv_merge8(v, ii, pv, pi);
}

// ---------------- init: mask dtype detection + decay chain + flag reset --------
__global__ void init_kernel(const unsigned char* __restrict__ mask) {
    __shared__ unsigned char anyf[TT];
    int tid = threadIdx.x;
    if (tid < NG) { g_fscore[tid] = 0; g_ffused[tid] = 0; }
    if (tid < 64) g_fvt[tid] = 0;
    if (tid == 0) {
        const unsigned* w = (const unsigned*)mask;
        bool okf = true, oki = true, sawf = false, sawi = false;
        for (int i = 0; i < 1024; i++) {
            unsigned v = w[i];
            if (v == 0x3F800000u) sawf = true; else if (v != 0u) okf = false;
            if (v == 1u)          sawi = true; else if (v != 0u) oki = false;
        }
        int kind = 2;
        if (okf && sawf) kind = 0;
        else if (oki && sawi) kind = 1;
        g_mask_kind = kind;
    }
    __syncthreads();
    int kind = g_mask_kind;
    if (tid < TT) {
        int t = tid;
        bool any = false;
        for (int b = 0; b < NBATCH; b++) {
            int idx = b * TT + t;
            bool m;
            if (kind == 0)      m = ((const float*)mask)[idx] != 0.0f;
            else if (kind == 1) m = ((const int*)mask)[idx] != 0;
            else                m = mask[idx] != 0;
            any = any || m;
        }
        anyf[t] = any ? 1 : 0;
    }
    __syncthreads();
    if (tid == 0) {
        float c = 1.0f;
        for (int t = 0; t < TT; t++) {
            g_cpre[t] = c;
            if (anyf[t]) c *= DECAYF;
            g_cpost[t] = c;
        }
    }
}

// ---------------- fp32 -> bf16 hi/lo split (elementwise) ----------------
__global__ __launch_bounds__(256) void conv_split(const float* __restrict__ s,
                                                  __nv_bfloat16* __restrict__ hi,
                                                  __nv_bfloat16* __restrict__ lo, int n) {
    int i = blockIdx.x * 256 + threadIdx.x;
    if (i < n) {
        float v = s[i];
        __nv_bfloat16 h = __float2bfloat16_rn(v);
        hi[i] = h;
        lo[i] = __float2bfloat16_rn(v - __bfloat162float(h));
    }
}

// ---------------- fp32 [R][C] -> bf16 hi/lo transposed [C][R] ----------------
__global__ __launch_bounds__(256) void conv_T(const float* __restrict__ src,
                                              __nv_bfloat16* __restrict__ dhi,
                                              __nv_bfloat16* __restrict__ dlo,
                                              int R, int C) {
    __shared__ float t[32][33];
    int c0 = blockIdx.x * 32, r0 = blockIdx.y * 32;
    int tx = threadIdx.x & 31, ty = threadIdx.x >> 5;
    #pragma unroll
    for (int j = 0; j < 32; j += 8)
        t[ty + j][tx] = src[(size_t)(r0 + ty + j) * C + c0 + tx];
    __syncthreads();
    #pragma unroll
    for (int j = 0; j < 32; j += 8) {
        float v = t[tx][ty + j];
        __nv_bfloat16 h = __float2bfloat16_rn(v);
        __nv_bfloat16 l = __float2bfloat16_rn(v - __bfloat162float(h));
        size_t o = (size_t)(c0 + ty + j) * R + r0 + tx;
        dhi[o] = h; dlo[o] = l;
    }
}

// ---------------- mma.sync bf16-split GEMM ----------------
__device__ __forceinline__ void gemm_load_chunk(
    uint32_t sbuf, int tid, int m0, int n0, int c, int K,
    const __nv_bfloat16* __restrict__ Ahi, const __nv_bfloat16* __restrict__ Alo,
    const __nv_bfloat16* __restrict__ Bhi, const __nv_bfloat16* __restrict__ Blo)
{
    #pragma unroll
    for (int i = 0; i < 8; i++) {
        int idx = tid + i * 256;          // 0..2047
        int piece = idx >> 9;             // 0..3
        int j = idx & 511;
        int row = j >> 2;
        int cv = (j & 3) * 8;
        const __nv_bfloat16* g;
        int grow;
        if (piece == 0)      { g = Ahi; grow = m0 + row; }
        else if (piece == 1) { g = Alo; grow = m0 + row; }
        else if (piece == 2) { g = Bhi; grow = n0 + row; }
        else                 { g = Blo; grow = n0 + row; }
        const void* ga = g + (size_t)grow * K + c * BK + cv;
        uint32_t sa = sbuf + (uint32_t)piece * PCH + (uint32_t)row * 80 + (uint32_t)cv * 2;
        cp_async16(sa, ga);
    }
    cp_commit();
}

template<int ACT>
__global__ __launch_bounds__(256) void gemm_mma(
    const __nv_bfloat16* __restrict__ Ahi, const __nv_bfloat16* __restrict__ Alo,
    const __nv_bfloat16* __restrict__ Bhi, const __nv_bfloat16* __restrict__ Blo,
    const float* __restrict__ bias, float* __restrict__ Cf,
    __nv_bfloat16* __restrict__ Chi, __nv_bfloat16* __restrict__ Clo,
    int K, int Ntot)
{
    extern __shared__ char smc[];
    int tid = threadIdx.x, lane = tid & 31, wid = tid >> 5;
    int wm = wid >> 2, wn = wid & 3;          // warp tile: 64 rows x 32 cols
    int m0 = blockIdx.y * BM, n0 = blockIdx.x * BN;
    int nch = K / BK;
    uint32_t sbase = smem_u32(smc);

    float acc[4][4][4];
    #pragma unroll
    for (int a = 0; a < 4; a++)
        #pragma unroll
        for (int b = 0; b < 4; b++)
            #pragma unroll
            for (int q = 0; q < 4; q++) acc[a][b][q] = 0.0f;

    gemm_load_chunk(sbase, tid, m0, n0, 0, K, Ahi, Alo, Bhi, Blo);
    cp_wait_all();
    __syncthreads();

    for (int c = 0; c < nch; c++) {
        int buf = c & 1;
        if (c + 1 < nch)
            gemm_load_chunk(sbase + (buf ^ 1) * BUFSZ, tid, m0, n0, c + 1, K,
                            Ahi, Alo, Bhi, Blo);
        uint32_t ab = sbase + (uint32_t)buf * BUFSZ;
        #pragma unroll
        for (int kk = 0; kk < 2; kk++) {
            int k0 = kk * 16;
            uint32_t bh[4][2], bl[4][2];
            #pragma unroll
            for (int ni = 0; ni < 4; ni++) {
                int nrow = wn * 32 + ni * 8 + (lane & 7);
                int ncol = k0 + ((lane >> 3) & 1) * 8;
                uint32_t ad = ab + 2 * PCH + (uint32_t)nrow * 80 + (uint32_t)ncol * 2;
                ldmatrix_x2(bh[ni], ad);
                ldmatrix_x2(bl[ni], ad + PCH);
            }
            #pragma unroll
            for (int mi = 0; mi < 4; mi++) {
                int arow = wm * 64 + mi * 16 + (lane & 7) + ((lane >> 3) & 1) * 8;
                int acol = k0 + ((lane >> 4) & 1) * 8;
                uint32_t ad = ab + (uint32_t)arow * 80 + (uint32_t)acol * 2;
                uint32_t ah[4], al[4];
                ldmatrix_x4(ah, ad);
                ldmatrix_x4(al, ad + PCH);
                #pragma unroll
                for (int ni = 0; ni < 4; ni++) {
                    mma16816(acc[mi][ni], ah, bh[ni]);
                    mma16816(acc[mi][ni], al, bh[ni]);
                    mma16816(acc[mi][ni], ah, bl[ni]);
                }
            }
        }
        cp_wait_all();
        __syncthreads();
    }

    #pragma unroll
    for (int mi = 0; mi < 4; mi++) {
        #pragma unroll
        for (int ni = 0; ni < 4; ni++) {
            int r = m0 + wm * 64 + mi * 16 + (lane >> 2);
            int cc = n0 + wn * 32 + ni * 8 + (lane & 3) * 2;
            float b0v = bias[cc], b1v = bias[cc + 1];
            float v0 = acc[mi][ni][0] + b0v, v1 = acc[mi][ni][1] + b1v;
            float v2 = acc[mi][ni][2] + b0v, v3 = acc[mi][ni][3] + b1v;
            if (ACT == 1) {
                v0 = gelu_tanh(v0); v1 = gelu_tanh(v1);
                v2 = gelu_tanh(v2); v3 = gelu_tanh(v3);
                __nv_bfloat16 h0 = __float2bfloat16_rn(v0);
                __nv_bfloat16 h1 = __float2bfloat16_rn(v1);
                __nv_bfloat16 h2 = __float2bfloat16_rn(v2);
                __nv_bfloat16 h3 = __float2bfloat16_rn(v3);
                __nv_bfloat16 l0 = __float2bfloat16_rn(v0 - __bfloat162float(h0));
                __nv_bfloat16 l1 = __float2bfloat16_rn(v1 - __bfloat162float(h1));
                __nv_bfloat16 l2 = __float2bfloat16_rn(v2 - __bfloat162float(h2));
                __nv_bfloat16 l3 = __float2bfloat16_rn(v3 - __bfloat162float(h3));
                uint32_t hp0 = (uint32_t)__bfloat16_as_ushort(h0) |
                               ((uint32_t)__bfloat16_as_ushort(h1) << 16);
                uint32_t hp1 = (uint32_t)__bfloat16_as_ushort(h2) |
                               ((uint32_t)__bfloat16_as_ushort(h3) << 16);
                uint32_t lp0 = (uint32_t)__bfloat16_as_ushort(l0) |
                               ((uint32_t)__bfloat16_as_ushort(l1) << 16);
                uint32_t lp1 = (uint32_t)__bfloat16_as_ushort(l2) |
                               ((uint32_t)__bfloat16_as_ushort(l3) << 16);
                *(uint32_t*)(Chi + (size_t)r * Ntot + cc) = hp0;
                *(uint32_t*)(Chi + (size_t)(r + 8) * Ntot + cc) = hp1;
                *(uint32_t*)(Clo + (size_t)r * Ntot + cc) = lp0;
                *(uint32_t*)(Clo + (size_t)(r + 8) * Ntot + cc) = lp1;
            } else {
                *(float2*)(Cf + (size_t)r * Ntot + cc) = make_float2(v0, v1);
                *(float2*)(Cf + (size_t)(r + 8) * Ntot + cc) = make_float2(v2, v3);
            }
        }
    }
}

// ---------------- LN + residual: g_h += LN(g_y) ----------------
__global__ __launch_bounds__(256) void ln_residual(const float* __restrict__ gam,
                                                   const float* __restrict__ bet) {
    __shared__ float red[40];
    int row = blockIdx.x, tid = threadIdx.x;
    const float* y = g_y + (size_t)row * DIM;
    float* h = g_h + (size_t)row * DIM;
    float xv[4], s = 0.0f;
    #pragma unroll
    for (int q = 0; q < 4; q++) { xv[q] = y[tid + q * 256]; s += xv[q]; }
    float mean = blockSum256(s, red, tid) * (1.0f / DIM);
    float vs = 0.0f;
    #pragma unroll
    for (int q = 0; q < 4; q++) { float d = xv[q] - mean; vs += d * d; }
    float var = blockSum256(vs, red, tid) * (1.0f / DIM);
    float rs = rsqrtf(var + 1e-5f);
    #pragma unroll
    for (int q = 0; q < 4; q++) {
        int d = tid + q * 256;
        h[d] += (xv[q] - mean) * rs * gam[d] + bet[d];
    }
}

// ---------------- persistent scan kernel (run-ahead, parity buffers) ----------
__global__ __launch_bounds__(256) void scan_kernel(
    const unsigned char* __restrict__ mask, float* __restrict__ out,
    const float* __restrict__ memK, const float* __restrict__ fuseW,
    const float* __restrict__ mlng, const float* __restrict__ mlnb)
{
    extern __shared__ float sm[];
    float* Ks  = sm + SM_KS;
    float* Wf  = sm + SM_WF;
    float* xc  = sm + SM_XC;
    float* red = sm + SM_RED;
    int*  redi = (int*)(sm + SM_REDI);
    float* slng = sm + SM_LNG;
    float* slnb = sm + SM_LNB;
    int tid = threadIdx.x, cta = blockIdx.x;
    int wrp = tid >> 5, lan = tid & 31;

    {
        const float4* src = (const float4*)(memK + (size_t)cta * 16 * DIM);
        float4* dst = (float4*)Ks;
        for (int i = tid; i < 4096; i += 256) dst[i] = src[i];
    }
    {
        int c0 = cta * 8;
        for (int i = tid; i < 8192; i += 256) {
            int d = i >> 3, j = i & 7;
            Wf[i] = fuseW[(size_t)(DIM + d) * DIM + c0 + j];   // v-part rows only
        }
    }
    for (int i = tid; i < 1024; i += 256) { slng[i] = mlng[i]; slnb[i] = mlnb[i]; }
    int kind = g_mask_kind;
    __syncthreads();

    // register prefetch of h_0
    float4 ph[8];
    #pragma unroll
    for (int k = 0; k < 8; k++) {
        int i = tid + k * 256; int b = i >> 8, d4 = i & 255;
        ph[k] = ((const float4*)(g_h + (size_t)(b * TT) * DIM))[d4];
    }

    for (int t = 0; t < TT; t++) {
        float cpre = g_cpre[t], cpost = g_cpost[t];
        int tgt = t + 1, p = t & 1;
        float* sc_p = g_scores + (size_t)p * SCO;
        float* sw_p = g_sw + (size_t)p * SWO;
        float* vt_p = g_vt + (size_t)p * NBATCH * DIM;
        float* fr_p = g_fusedraw + (size_t)p * NBATCH * DIM;

        // ---- xc h-half from prefetch ----
        #pragma unroll
        for (int k = 0; k < 8; k++) {
            int i = tid + k * 256; int b = i >> 8, d4 = i & 255;
            ((float4*)(xc + b * 2048))[d4] = ph[k];
        }
        __syncthreads();

        // ---- phase A: scores for this CTA's 16 K rows ----
        {
            int hh = lan >> 3, r8 = lan & 7;
            int r0 = 2 * wrp, r1 = r0 + 1;
            float a0[8], a1[8];
            #pragma unroll
            for (int b = 0; b < 8; b++) { a0[b] = 0.0f; a1[b] = 0.0f; }
            const float* K0 = Ks + r0 * 1024 + hh * 256 + r8 * 4;
            const float* K1 = Ks + r1 * 1024 + hh * 256 + r8 * 4;
            const float* hb = xc + hh * 256 + r8 * 4;
            #pragma unroll
            for (int j = 0; j < 8; j++) {
                int off = j * 32;
                float4 k0 = *(const float4*)(K0 + off);
                float4 k1 = *(const float4*)(K1 + off);
                #pragma unroll
                for (int b = 0; b < 8; b++) {
                    float4 hv = *(const float4*)(hb + b * 2048 + off);
                    a0[b] += k0.x * hv.x + k0.y * hv.y + k0.z * hv.z + k0.w * hv.w;
                    a1[b] += k1.x * hv.x + k1.y * hv.y + k1.z * hv.z + k1.w * hv.w;
                }
            }
            #pragma unroll
            for (int o = 4; o; o >>= 1) {
                #pragma unroll
                for (int b = 0; b < 8; b++) {
                    a0[b] += __shfl_xor_sync(0xFFFFFFFFu, a0[b], o);
                    a1[b] += __shfl_xor_sync(0xFFFFFFFFu, a1[b], o);
                }
            }
            float t0[8], t1[8];
            #pragma unroll
            for (int b = 0; b < 8; b++) { t0[b] = a0[b]; t1[b] = a1[b]; }
            #pragma unroll
            for (int o = 8; o <= 16; o <<= 1) {
                #pragma unroll
                for (int b = 0; b < 8; b++) {
                    t0[b] += __shfl_xor_sync(0xFFFFFFFFu, t0[b], o);
                    t1[b] += __shfl_xor_sync(0xFFFFFFFFu, t1[b], o);
                }
            }
            int s0 = cta * 16 + r0, s1 = s0 + 1;
            if (r8 == 0) {
                #pragma unroll
                for (int b = 0; b < 8; b++) {
                    sc_p[(size_t)(b * NH + hh) * NS + s0] = a0[b] * INV_SQRT_DH;
                    sc_p[(size_t)(b * NH + hh) * NS + s1] = a1[b] * INV_SQRT_DH;
                }
            }
            if (lan == 0) {
                #pragma unroll
                for (int b = 0; b < 8; b++) {
                    sw_p[b * NS + s0] = t0[b] * INV_SQRT_D;
                    sw_p[b * NS + s1] = t1[b] * INV_SQRT_D;
                }
            }
        }
        __syncthreads();
        if (tid == 0) st_rel(&g_fscore[cta], tgt);   // scores published

        // ---- phase B: top-k read (CTAs 0..31) + write stats (CTAs 32..39) ----
        if (cta < 32) {
            wait_n(g_fscore, NG, tgt, tid);
            int b = cta >> 2, h = cta & 3;
            const float* sc = sc_p + (size_t)(b * NH + h) * NS;
            float v[8]; int ii[8];
            #pragma unroll
            for (int k = 0; k < 8; k++) { v[k] = sc[k * 256 + tid]; ii[k] = k * 256 + tid; }
            kv_sort8(v, ii);
            kv_bfly(v, ii, 1); kv_bfly(v, ii, 2); kv_bfly(v, ii, 4);
            kv_bfly(v, ii, 8); kv_bfly(v, ii, 16);
            if (lan == 0) {
                #pragma unroll
                for (int e = 0; e < 8; e++) { red[wrp * 8 + e] = v[e]; redi[wrp * 8 + e] = ii[e]; }
            }
            __syncthreads();
            if (wrp == 0) {
                float v2[8]; int i2[8];
                if (lan < 8) {
                    #pragma unroll
                    for (int e = 0; e < 8; e++) { v2[e] = red[lan * 8 + e]; i2[e] = redi[lan * 8 + e]; }
                } else {
                    #pragma unroll
                    for (int e = 0; e < 8; e++) { v2[e] = -FLT_MAX; i2[e] = 0x7FFFFFFF; }
                }
                {
                    float* v = v2; int* ii = i2;
                    kv_bfly(v, ii, 1); kv_bfly(v, ii, 2); kv_bfly(v, ii, 4);
                }
                if (lan == 0) {
                    #pragma unroll
                    for (int e = 0; e < 8; e++) { red[e] = v2[e]; redi[e] = i2[e]; }
                }
            }
            __syncthreads();
            float topv[NKTOP]; int topi[NKTOP];
            #pragma unroll
            for (int e = 0; e < 8; e++) { topv[e] = red[e]; topi[e] = redi[e]; }
            float w8[NKTOP], Z = 0.0f;
            #pragma unroll
            for (int k = 0; k < NKTOP; k++) { w8[k] = expf(topv[k] - topv[0]); Z += w8[k]; }
            float invZ = 1.0f / Z;
            float accv = 0.0f;
            #pragma unroll
            for (int k = 0; k < NKTOP; k++)
                accv += w8[k] * g_Vbuf[(size_t)topi[k] * DIM + h * NDh + tid];
            vt_p[b * DIM + h * NDh + tid] = accv * invZ * cpre;
            __syncthreads();
            if (tid == 0) st_rel(&g_fvt[cta], tgt);
        } else if (cta < 40) {
            wait_n(g_fscore, NG, tgt, tid);
            int b = cta - 32;
            const float* swp = sw_p + b * NS;
            float v[8];
            #pragma unroll
            for (int k = 0; k < 8; k++) v[k] = swp[k * 256 + tid];
            float bv = -3.4e38f; int bi = 0x7FFFFFFF;
            #pragma unroll
            for (int k = 0; k < 8; k++) {
                int ix = k * 256 + tid;
                if (v[k] > bv || (v[k] == bv && ix < bi)) { bv = v[k]; bi = ix; }
            }
            float mv; int mi;
            blockArgMax256(bv, bi, red, redi, tid, mv, mi);
            float se = 0.0f;
            #pragma unroll
            for (int k = 0; k < 8; k++) se += expf(v[k] - mv);
            float Z = blockSum256(se, red, tid);
            if (tid == 0) {
                float surprise = 1.0f - 1.0f / Z;
                int midx = b * TT + t;
                float m;
                if (kind == 0)      m = ((const float*)mask)[midx];
                else if (kind == 1) m = (float)((const int*)mask)[midx];
                else                m = (float)mask[midx];
                float lr = (surprise > SURPRISE_TH ? LR_FAST : LR_DEEP);
                lr *= (m != 0.0f ? 1.0f : 0.0f);
                g_slot[p][b] = mi;
                g_lr[p][b] = lr;
            }
            __syncthreads();
            if (tid == 0) st_rel(&g_fvt[cta], tgt);
        }

        // ---- wait for v_t + write stats ----
        wait_n(g_fvt, 40, tgt, tid);

        // ---- load v_t into xc[b][1024..2047] ----
        for (int i = tid; i < 2048; i += 256) {
            int b = i >> 8, d4 = i & 255;
            ((float4*)(xc + b * 2048 + 1024))[d4] =
                ((const float4*)(vt_p + b * DIM))[d4];
        }
        __syncthreads();

        // ---- phase C (v-half only; h-part precomputed in g_y) ----
        if (tid < 128) {
            int w = tid >> 5, l = tid & 31;
            int b0 = w * 2;
            float A0[8], A1[8];
            #pragma unroll
            for (int c = 0; c < 8; c++) { A0[c] = 0.0f; A1[c] = 0.0f; }
            for (int j = 0; j < 32; j++) {
                int d = j * 32 + l;
                float4 w0 = *(const float4*)(Wf + d * 8);
                float4 w1 = *(const float4*)(Wf + d * 8 + 4);
                float x0 = xc[b0 * 2048 + 1024 + d];
                float x1 = xc[(b0 + 1) * 2048 + 1024 + d];
                A0[0] += x0 * w0.x; A0[1] += x0 * w0.y; A0[2] += x0 * w0.z; A0[3] += x0 * w0.w;
                A0[4] += x0 * w1.x; A0[5] += x0 * w1.y; A0[6] += x0 * w1.z; A0[7] += x0 * w1.w;
                A1[0] += x1 * w0.x; A1[1] += x1 * w0.y; A1[2] += x1 * w0.z; A1[3] += x1 * w0.w;
                A1[4] += x1 * w1.x; A1[5] += x1 * w1.y; A1[6] += x1 * w1.z; A1[7] += x1 * w1.w;
            }
            #pragma unroll
            for (int o = 16; o; o >>= 1) {
                #pragma unroll
                for (int c = 0; c < 8; c++) {
                    A0[c] += __shfl_xor_sync(0xFFFFFFFFu, A0[c], o);
                    A1[c] += __shfl_xor_sync(0xFFFFFFFFu, A1[c], o);
                }
            }
            if (l == 0) {
                int c0 = cta * 8;
                const float* fh0 = g_y + (size_t)(b0 * TT + t) * DIM + c0;
                const float* fh1 = g_y + (size_t)((b0 + 1) * TT + t) * DIM + c0;
                #pragma unroll
                for (int c = 0; c < 8; c++) {
                    fr_p[b0 * DIM + c0 + c] = A0[c] + fh0[c];
                    fr_p[(b0 + 1) * DIM + c0 + c] = A1[c] + fh1[c];
                }
            }
        }
        __syncthreads();
        if (tid == 0) st_rel(&g_ffused[cta], tgt);

        // ---- prefetch h_{t+1} into registers (hides L2 latency under tail) ----
        if (t + 1 < TT) {
            #pragma unroll
            for (int k = 0; k < 8; k++) {
                int i = tid + k * 256; int b = i >> 8, d4 = i & 255;
                ph[k] = ((const float4*)(g_h + (size_t)(b * TT + t + 1) * DIM))[d4];
            }
        }

        // ---- only output-LN CTAs (120..127) and slot owners take the full wait ----
        bool is_d = (cta >= 120);
        bool is_owner = false;
        #pragma unroll
        for (int b = 0; b < 8; b++) if ((g_slot[p][b] >> 4) == cta) is_owner = true;
        if (is_d || is_owner) {
            wait_n(g_ffused, NG, tgt, tid);

            // ---- phase D: LN(fused_raw + h_t) -> out ----
            if (is_d) {
                int b = cta - 120;
                float xv[4], s = 0.0f;
                #pragma unroll
                for (int q = 0; q < 4; q++) {
                    int d = tid + q * 256;
                    xv[q] = fr_p[b * DIM + d] + xc[b * 2048 + d];
                    s += xv[q];
                }
                float mean = blockSum256(s, red, tid) * (1.0f / DIM);
                float vs = 0.0f;
                #pragma unroll
                for (int q = 0; q < 4; q++) { float dd = xv[q] - mean; vs += dd * dd; }
                float var = blockSum256(vs, red, tid) * (1.0f / DIM);
                float rs = rsqrtf(var + 1e-5f);
                float* o = out + ((size_t)(b * TT + t)) * DIM;
                #pragma unroll
                for (int q = 0; q < 4; q++) {
                    int d = tid + q * 256;
                    o[d] = (xv[q] - mean) * rs * slng[d] + slnb[d];
                }
            }

            // ---- phase E: owner CTAs update their K rows + Vbuf ----
            if (is_owner) {
                #pragma unroll 1
                for (int b = 0; b < 8; b++) {
                    if ((g_slot[p][b] >> 4) == cta) {
                        float s = 0.0f;
                        #pragma unroll
                        for (int q = 0; q < 4; q++) {
                            int d = tid + q * 256;
                            s += fr_p[b * DIM + d] + xc[b * 2048 + d];
                        }
                        float mean = blockSum256(s, red, tid) * (1.0f / DIM);
                        float vs = 0.0f;
                        #pragma unroll
                        for (int q = 0; q < 4; q++) {
                            int d = tid + q * 256;
                            float dd = fr_p[b * DIM + d] + xc[b * 2048 + d] - mean;
                            vs += dd * dd;
                        }
                        float var = blockSum256(vs, red, tid) * (1.0f / DIM);
                        if (tid == 0) { red[40 + b] = mean; red[48 + b] = rsqrtf(var + 1e-5f); }
                    }
                }
                __syncthreads();
                float invcp = 1.0f / cpost;
                #pragma unroll 1
                for (int r = 0; r < 16; r++) {
                    int srow = cta * 16 + r;
                    bool hit = false;
                    #pragma unroll
                    for (int b = 0; b < 8; b++) if (g_slot[p][b] == srow) hit = true;
                    if (!hit) continue;
                    #pragma unroll
                    for (int q = 0; q < 4; q++) {
                        int d = tid + q * 256;
                        float kpre = Ks[r * 1024 + d];
                        float vpre = g_Vbuf[(size_t)srow * DIM + d];
                        float ka = 0.0f, va = 0.0f;
                        #pragma unroll
                        for (int b = 0; b < 8; b++) {
                            if (g_slot[p][b] == srow) {
                                float lr = g_lr[p][b];
                                float f = fr_p[b * DIM + d] + xc[b * 2048 + d];
                                float vw = (f - red[40 + b]) * red[48 + b] * slng[d] + slnb[d];
                                ka += lr * (xc[b * 2048 + d] - kpre);
                                va += lr * invcp * (vw - cpost * vpre);
                            }
                        }
                        Ks[r * 1024 + d] = kpre + ka;
                        g_Vbuf[(size_t)srow * DIM + d] = vpre + va;
                    }
                }
            }
        }
        __syncthreads();
    }
}

// ---------------- launch ----------------
extern "C" void kernel_launch(void* const* d_in, const int* in_sizes, int n_in,
                              void* d_out, int out_size) {
    const float* x      = (const float*)d_in[0];
    const unsigned char* mask = (const unsigned char*)d_in[1];
    const float* W1     = (const float*)d_in[2];
    const float* b1     = (const float*)d_in[3];
    const float* W2     = (const float*)d_in[4];
    const float* b2     = (const float*)d_in[5];
    const float* ln_g   = (const float*)d_in[6];
    const float* ln_b   = (const float*)d_in[7];
    const float* fuse_W = (const float*)d_in[8];
    const float* fuse_b = (const float*)d_in[9];
    const float* mln_g  = (const float*)d_in[10];
    const float* mln_b  = (const float*)d_in[11];
    const float* mem_K  = (const float*)d_in[12];
    const float* mem_V  = (const float*)d_in[13];
    float* out = (float*)d_out;

    float *p_h, *p_y, *p_V;
    __nv_bfloat16 *p_hhi, *p_hlo, *p_thi, *p_tlo, *p_w1h, *p_w1l, *p_w2h, *p_w2l;
    cudaGetSymbolAddress((void**)&p_h, g_h);
    cudaGetSymbolAddress((void**)&p_y, g_y);
    cudaGetSymbolAddress((void**)&p_V, g_Vbuf);
    cudaGetSymbolAddress((void**)&p_hhi, g_hhi);
    cudaGetSymbolAddress((void**)&p_hlo, g_hlo);
    cudaGetSymbolAddress((void**)&p_thi, g_thi);
    cudaGetSymbolAddress((void**)&p_tlo, g_tlo);
    cudaGetSymbolAddress((void**)&p_w1h, g_w1thi);
    cudaGetSymbolAddress((void**)&p_w1l, g_w1tlo);
    cudaGetSymbolAddress((void**)&p_w2h, g_w2thi);
    cudaGetSymbolAddress((void**)&p_w2l, g_w2tlo);

    cudaMemcpyAsync(p_h, x, (size_t)NBATCH * TT * DIM * 4, cudaMemcpyDeviceToDevice, 0);
    cudaMemcpyAsync(p_V, mem_V, (size_t)NS * DIM * 4, cudaMemcpyDeviceToDevice, 0);
    init_kernel<<<1, 512>>>(mask);

    cudaFuncSetAttribute(gemm_mma<1>, cudaFuncAttributeMaxDynamicSharedMemorySize, GEMM_SMEM_BYTES);
    cudaFuncSetAttribute(gemm_mma<0>, cudaFuncAttributeMaxDynamicSharedMemorySize, GEMM_SMEM_BYTES);

    const int M = NBATCH * TT;           // 4096
    for (int i = 0; i < 2; i++) {
        conv_split<<<(M * DIM + 255) / 256, 256>>>(p_h, p_hhi, p_hlo, M * DIM);
        conv_T<<<dim3(2 * DIM / 32, DIM / 32), 256>>>(
            W1 + (size_t)i * DIM * 2 * DIM, p_w1h, p_w1l, DIM, 2 * DIM);
        gemm_mma<1><<<dim3(2 * DIM / BN, M / BM), 256, GEMM_SMEM_BYTES>>>(
            p_hhi, p_hlo, p_w1h, p_w1l, b1 + (size_t)i * 2 * DIM,
            nullptr, p_thi, p_tlo, DIM, 2 * DIM);
        conv_T<<<dim3(DIM / 32, 2 * DIM / 32), 256>>>(
            W2 + (size_t)i * 2 * DIM * DIM, p_w2h, p_w2l, 2 * DIM, DIM);
        gemm_mma<0><<<dim3(DIM / BN, M / BM), 256, GEMM_SMEM_BYTES>>>(
            p_thi, p_tlo, p_w2h, p_w2l, b2 + (size_t)i * DIM,
            p_y, nullptr, nullptr, 2 * DIM, DIM);
        ln_residual<<<M, 256>>>(ln_g + (size_t)i * DIM, ln_b + (size_t)i * DIM);
    }

    // fused_h = h @ fuse_W[0:1024] + fuse_b  (reuses g_y)
    conv_split<<<(M * DIM + 255) / 256, 256>>>(p_h, p_hhi, p_hlo, M * DIM);
    conv_T<<<dim3(DIM / 32, DIM / 32), 256>>>(fuse_W, p_w1h, p_w1l, DIM, DIM);
    gemm_mma<0><<<dim3(DIM / BN, M / BM), 256, GEMM_SMEM_BYTES>>>(
        p_hhi, p_hlo, p_w1h, p_w1l, fuse_b,
        p_y, nullptr, nullptr, DIM, DIM);

    cudaFuncSetAttribute(scan_kernel, cudaFuncAttributeMaxDynamicSharedMemorySize, SMEM_BYTES);
    scan_kernel<<<NG, 256, SMEM_BYTES>>>(mask, out, mem_K, fuse_W, mln_g, mln_b);
}

// round 14
// speedup vs baseline: 1.0393x; 1.0393x over previous
#include <cuda_runtime.h>
#include <cuda_bf16.h>
#include <cstdint>
#include <math.h>
#include <float.h>

#define NBATCH 8
#define TT 512
#define DIM 1024
#define NS 2048
#define NH 4
#define NKTOP 8
#define NDh 256
#define NG 128
#define LR_FAST 1.0f
#define LR_DEEP 0.1f
#define SURPRISE_TH 0.6f
#define DECAYF 0.9995f
#define INV_SQRT_DH 0.0625f
#define INV_SQRT_D  0.03125f

// scan smem layout (floats)
#define SM_KS 0
#define SM_WF 16384          // 8192 floats: transposed v-part of fuse_W as [4][1024] float2
#define SM_XC 24576          // 8*2048
#define SM_RED 40960         // 128 floats (aliased: u64 top-k lists / LN stats 40..55)
#define SM_LNG 41088
#define SM_LNB 42112
#define SMEM_FLOATS 43136
#define SMEM_BYTES (SMEM_FLOATS * 4)

#define BM 128
#define BN 128
#define BK 32
#define PCH 10240
#define BUFSZ (4 * PCH)
#define GEMM_SMEM_BYTES (2 * BUFSZ)

#define SCO (NBATCH * NH * NS)
#define SWO (NBATCH * NS)

__device__ float g_h[NBATCH * TT * DIM];
__device__ float g_y[NBATCH * TT * DIM];
__device__ float g_Vbuf[NS * DIM];
__device__ float g_scores[2 * SCO];
__device__ float g_sw[2 * SWO];
__device__ float g_vt[2 * NBATCH * DIM];
__device__ float g_frall[(size_t)TT * NBATCH * DIM];   // fused_raw for all steps
__device__ int   g_slot[2][NBATCH];
__device__ float g_lr[2][NBATCH];
__device__ float g_cpre[TT];
__device__ float g_cpost[TT];
__device__ int g_mask_kind;
__device__ int g_fscore[NG];
__device__ int g_fvt[64];
__device__ int g_ffused[NG];
__device__ __align__(16) __nv_bfloat16 g_hhi[NBATCH * TT * DIM];
__device__ __align__(16) __nv_bfloat16 g_hlo[NBATCH * TT * DIM];
__device__ __align__(16) __nv_bfloat16 g_thi[NBATCH * TT * 2 * DIM];
__device__ __align__(16) __nv_bfloat16 g_tlo[NBATCH * TT * 2 * DIM];
__device__ __align__(16) __nv_bfloat16 g_w1thi[2 * DIM * DIM];
__device__ __align__(16) __nv_bfloat16 g_w1tlo[2 * DIM * DIM];
__device__ __align__(16) __nv_bfloat16 g_w2thi[2 * DIM * DIM];
__device__ __align__(16) __nv_bfloat16 g_w2tlo[2 * DIM * DIM];

// ---- base-PTX helpers ----
__device__ __forceinline__ uint32_t smem_u32(const void* p) {
    uint32_t a;
    asm("{ .reg .u64 t; cvta.to.shared.u64 t, %1; cvt.u32.u64 %0, t; }" : "=r"(a) : "l"(p));
    return a;
}
__device__ __forceinline__ void cp_async16(uint32_t saddr, const void* gaddr) {
    asm volatile("cp.async.cg.shared.global [%0], [%1], 16;" :: "r"(saddr), "l"(gaddr));
}
__device__ __forceinline__ void cp_commit() { asm volatile("cp.async.commit_group;" ::: "memory"); }
__device__ __forceinline__ void cp_wait_all() { asm volatile("cp.async.wait_group 0;" ::: "memory"); }
__device__ __forceinline__ void ldmatrix_x4(uint32_t* r, uint32_t addr) {
    asm volatile("ldmatrix.sync.aligned.m8n8.x4.shared.b16 {%0,%1,%2,%3}, [%4];"
        : "=r"(r[0]), "=r"(r[1]), "=r"(r[2]), "=r"(r[3]) : "r"(addr));
}
__device__ __forceinline__ void ldmatrix_x2(uint32_t* r, uint32_t addr) {
    asm volatile("ldmatrix.sync.aligned.m8n8.x2.shared.b16 {%0,%1}, [%2];"
        : "=r"(r[0]), "=r"(r[1]) : "r"(addr));
}
__device__ __forceinline__ void mma16816(float* c, const uint32_t* a, const uint32_t* b) {
    asm volatile("mma.sync.aligned.m16n8k16.row.col.f32.bf16.bf16.f32 "
        "{%0,%1,%2,%3}, {%4,%5,%6,%7}, {%8,%9}, {%0,%1,%2,%3};"
        : "+f"(c[0]), "+f"(c[1]), "+f"(c[2]), "+f"(c[3])
        : "r"(a[0]), "r"(a[1]), "r"(a[2]), "r"(a[3]), "r"(b[0]), "r"(b[1]));
}
__device__ __forceinline__ void st_rel(int* p, int v) {
    asm volatile("st.release.gpu.global.s32 [%0], %1;" :: "l"(p), "r"(v) : "memory");
}
__device__ __forceinline__ int ld_acq(const int* p) {
    int v;
    asm volatile("ld.acquire.gpu.global.s32 %0, [%1];" : "=r"(v) : "l"(p) : "memory");
    return v;
}
__device__ __forceinline__ void wait_n(const int* flags, int n, int tgt, int tid) {
    for (;;) {
        int v = (tid < n) ? ld_acq(flags + tid) : tgt;
        if (__syncthreads_and(v >= tgt)) break;
    }
}

__device__ __forceinline__ float gelu_tanh(float x) {
    const float c = 0.7978845608028654f;
    float t = tanhf(c * (x + 0.044715f * x * x * x));
    return 0.5f * x * (1.0f + t);
}
__device__ __forceinline__ float blockSum256(float v, float* red, int tid) {
    #pragma unroll
    for (int o = 16; o; o >>= 1) v += __shfl_xor_sync(0xFFFFFFFFu, v, o);
    if ((tid & 31) == 0) red[tid >> 5] = v;
    __syncthreads();
    if (tid < 32) {
        float x = (tid < 8) ? red[tid] : 0.0f;
        #pragma unroll
        for (int o = 4; o; o >>= 1) x += __shfl_xor_sync(0xFFFFFFFFu, x, o);
        if (tid == 0) red[32] = x;
    }
    __syncthreads();
    float r = red[32];
    __syncthreads();
    return r;
}

// ---- packed (value desc, index asc) top-8 ----
__device__ __forceinline__ unsigned long long packkv(float v, int idx) {
    uint32_t u = __float_as_uint(v);
    uint32_t k = (u & 0x80000000u) ? ~u : (u | 0x80000000u);
    return ((unsigned long long)k << 32) | (uint32_t)(~idx);
}
__device__ __forceinline__ int unpack_idx(unsigned long long p) { return (int)(~(uint32_t)p); }
__device__ __forceinline__ float unpack_val(unsigned long long p) {
    uint32_t k = (uint32_t)(p >> 32);
    uint32_t u = (k & 0x80000000u) ? (k & 0x7FFFFFFFu) : ~k;
    return __uint_as_float(u);
}
#define PCE(x, y) { if (P[x] < P[y]) { unsigned long long _t = P[x]; P[x] = P[y]; P[y] = _t; } }
__device__ __forceinline__ void psort8(unsigned long long* P) {
    PCE(0,1) PCE(2,3) PCE(4,5) PCE(6,7)
    PCE(0,2) PCE(1,3) PCE(4,6) PCE(5,7)
    PCE(1,2) PCE(5,6)
    PCE(0,4) PCE(1,5) PCE(2,6) PCE(3,7)
    PCE(2,4) PCE(3,5)
    PCE(1,2) PCE(3,4) PCE(5,6)
}
__device__ __forceinline__ void pmerge8(unsigned long long* P, const unsigned long long* Q) {
    #pragma unroll
    for (int e = 0; e < 8; e++) { unsigned long long q = Q[7 - e]; if (P[e] < q) P[e] = q; }
    PCE(0,4) PCE(1,5) PCE(2,6) PCE(3,7)
    PCE(0,2) PCE(1,3) PCE(4,6) PCE(5,7)
    PCE(0,1) PCE(2,3) PCE(4,5) PCE(6,7)
}
__device__ __forceinline__ void pbfly(unsigned long long* P, int off) {
    unsigned long long Q[8];
    #pragma unroll
    for (int e = 0; e < 8; e++) Q[e] = __shfl_xor_sync(0xFFFFFFFFu, P[e], off);
    pmerge8(P, Q);
}

// ---- init ----
__global__ void init_kernel(const unsigned char* __restrict__ mask) {
    __shared__ unsigned char anyf[TT];
    int tid = threadIdx.x;
    if (tid < NG) { g_fscore[tid] = 0; g_ffused[tid] = 0; }
    if (tid < 64) g_fvt[tid] = 0;
    if (tid == 0) {
        const unsigned* w = (const unsigned*)mask;
        bool okf = true, oki = true, sawf = false, sawi = false;
        for (int i = 0; i < 1024; i++) {
            unsigned v = w[i];
            if (v == 0x3F800000u) sawf = true; else if (v != 0u) okf = false;
            if (v == 1u)          sawi = true; else if (v != 0u) oki = false;
        }
        int kind = 2;
        if (okf && sawf) kind = 0;
        else if (oki && sawi) kind = 1;
        g_mask_kind = kind;
    }
    __syncthreads();
    int kind = g_mask_kind;
    if (tid < TT) {
        bool any = false;
        for (int b = 0; b < NBATCH; b++) {
            int idx = b * TT + tid;
            bool m;
            if (kind == 0)      m = ((const float*)mask)[idx] != 0.0f;
            else if (kind == 1) m = ((const int*)mask)[idx] != 0;
            else                m = mask[idx] != 0;
            any = any || m;
        }
        anyf[tid] = any ? 1 : 0;
    }
    __syncthreads();
    if (tid == 0) {
        float c = 1.0f;
        for (int t = 0; t < TT; t++) {
            g_cpre[t] = c;
            if (anyf[t]) c *= DECAYF;
            g_cpost[t] = c;
        }
    }
}

__global__ __launch_bounds__(256) void conv_split(const float* __restrict__ s,
                                                  __nv_bfloat16* __restrict__ hi,
                                                  __nv_bfloat16* __restrict__ lo, int n) {
    int i = blockIdx.x * 256 + threadIdx.x;
    if (i < n) {
        float v = s[i];
        __nv_bfloat16 h = __float2bfloat16_rn(v);
        hi[i] = h;
        lo[i] = __float2bfloat16_rn(v - __bfloat162float(h));
    }
}

__global__ __launch_bounds__(256) void conv_T(const float* __restrict__ src,
                                              __nv_bfloat16* __restrict__ dhi,
                                              __nv_bfloat16* __restrict__ dlo,
                                              int R, int C) {
    __shared__ float t[32][33];
    int c0 = blockIdx.x * 32, r0 = blockIdx.y * 32;
    int tx = threadIdx.x & 31, ty = threadIdx.x >> 5;
    #pragma unroll
    for (int j = 0; j < 32; j += 8)
        t[ty + j][tx] = src[(size_t)(r0 + ty + j) * C + c0 + tx];
    __syncthreads();
    #pragma unroll
    for (int j = 0; j < 32; j += 8) {
        float v = t[tx][ty + j];
        __nv_bfloat16 h = __float2bfloat16_rn(v);
        __nv_bfloat16 l = __float2bfloat16_rn(v - __bfloat162float(h));
        size_t o = (size_t)(c0 + ty + j) * R + r0 + tx;
        dhi[o] = h; dlo[o] = l;
    }
}

// ---- mma.sync bf16-split GEMM ----
__device__ __forceinline__ void gemm_load_chunk(
    uint32_t sbuf, int tid, int m0, int n0, int c, int K,
    const __nv_bfloat16* __restrict__ Ahi, const __nv_bfloat16* __restrict__ Alo,
    const __nv_bfloat16* __restrict__ Bhi, const __nv_bfloat16* __restrict__ Blo)
{
    #pragma unroll
    for (int i = 0; i < 8; i++) {
        int idx = tid + i * 256;
        int piece = idx >> 9;
        int j = idx & 511;
        int row = j >> 2;
        int cv = (j & 3) * 8;
        const __nv_bfloat16* g;
        int grow;
        if (piece == 0)      { g = Ahi; grow = m0 + row; }
        else if (piece == 1) { g = Alo; grow = m0 + row; }
        else if (piece == 2) { g = Bhi; grow = n0 + row; }
        else                 { g = Blo; grow = n0 + row; }
        const void* ga = g + (size_t)grow * K + c * BK + cv;
        uint32_t sa = sbuf + (uint32_t)piece * PCH + (uint32_t)row * 80 + (uint32_t)cv * 2;
        cp_async16(sa, ga);
    }
    cp_commit();
}

template<int ACT>
__global__ __launch_bounds__(256) void gemm_mma(
    const __nv_bfloat16* __restrict__ Ahi, const __nv_bfloat16* __restrict__ Alo,
    const __nv_bfloat16* __restrict__ Bhi, const __nv_bfloat16* __restrict__ Blo,
    const float* __restrict__ bias, float* __restrict__ Cf,
    __nv_bfloat16* __restrict__ Chi, __nv_bfloat16* __restrict__ Clo,
    int K, int Ntot)
{
    extern __shared__ char smc[];
    int tid = threadIdx.x, lane = tid & 31, wid = tid >> 5;
    int wm = wid >> 2, wn = wid & 3;
    int m0 = blockIdx.y * BM, n0 = blockIdx.x * BN;
    int nch = K / BK;
    uint32_t sbase = smem_u32(smc);

    float acc[4][4][4];
    #pragma unroll
    for (int a = 0; a < 4; a++)
        #pragma unroll
        for (int b = 0; b < 4; b++)
            #pragma unroll
            for (int q = 0; q < 4; q++) acc[a][b][q] = 0.0f;

    gemm_load_chunk(sbase, tid, m0, n0, 0, K, Ahi, Alo, Bhi, Blo);
    cp_wait_all();
    __syncthreads();

    for (int c = 0; c < nch; c++) {
        int buf = c & 1;
        if (c + 1 < nch)
            gemm_load_chunk(sbase + (buf ^ 1) * BUFSZ, tid, m0, n0, c + 1, K,
                            Ahi, Alo, Bhi, Blo);
        uint32_t ab = sbase + (uint32_t)buf * BUFSZ;
        #pragma unroll
        for (int kk = 0; kk < 2; kk++) {
            int k0 = kk * 16;
            uint32_t bh[4][2], bl[4][2];
            #pragma unroll
            for (int ni = 0; ni < 4; ni++) {
                int nrow = wn * 32 + ni * 8 + (lane & 7);
                int ncol = k0 + ((lane >> 3) & 1) * 8;
                uint32_t ad = ab + 2 * PCH + (uint32_t)nrow * 80 + (uint32_t)ncol * 2;
                ldmatrix_x2(bh[ni], ad);
                ldmatrix_x2(bl[ni], ad + PCH);
            }
            #pragma unroll
            for (int mi = 0; mi < 4; mi++) {
                int arow = wm * 64 + mi * 16 + (lane & 7) + ((lane >> 3) & 1) * 8;
                int acol = k0 + ((lane >> 4) & 1) * 8;
                uint32_t ad = ab + (uint32_t)arow * 80 + (uint32_t)acol * 2;
                uint32_t ah[4], al[4];
                ldmatrix_x4(ah, ad);
                ldmatrix_x4(al, ad + PCH);
                #pragma unroll
                for (int ni = 0; ni < 4; ni++) {
                    mma16816(acc[mi][ni], ah, bh[ni]);
                    mma16816(acc[mi][ni], al, bh[ni]);
                    mma16816(acc[mi][ni], ah, bl[ni]);
                }
            }
        }
        cp_wait_all();
        __syncthreads();
    }

    #pragma unroll
    for (int mi = 0; mi < 4; mi++) {
        #pragma unroll
        for (int ni = 0; ni < 4; ni++) {
            int r = m0 + wm * 64 + mi * 16 + (lane >> 2);
            int cc = n0 + wn * 32 + ni * 8 + (lane & 3) * 2;
            float b0v = bias[cc], b1v = bias[cc + 1];
            float v0 = acc[mi][ni][0] + b0v, v1 = acc[mi][ni][1] + b1v;
            float v2 = acc[mi][ni][2] + b0v, v3 = acc[mi][ni][3] + b1v;
            if (ACT == 1) {
                v0 = gelu_tanh(v0); v1 = gelu_tanh(v1);
                v2 = gelu_tanh(v2); v3 = gelu_tanh(v3);
                __nv_bfloat16 h0 = __float2bfloat16_rn(v0);
                __nv_bfloat16 h1 = __float2bfloat16_rn(v1);
                __nv_bfloat16 h2 = __float2bfloat16_rn(v2);
                __nv_bfloat16 h3 = __float2bfloat16_rn(v3);
                __nv_bfloat16 l0 = __float2bfloat16_rn(v0 - __bfloat162float(h0));
                __nv_bfloat16 l1 = __float2bfloat16_rn(v1 - __bfloat162float(h1));
                __nv_bfloat16 l2 = __float2bfloat16_rn(v2 - __bfloat162float(h2));
                __nv_bfloat16 l3 = __float2bfloat16_rn(v3 - __bfloat162float(h3));
                uint32_t hp0 = (uint32_t)__bfloat16_as_ushort(h0) |
                               ((uint32_t)__bfloat16_as_ushort(h1) << 16);
                uint32_t hp1 = (uint32_t)__bfloat16_as_ushort(h2) |
                               ((uint32_t)__bfloat16_as_ushort(h3) << 16);
                uint32_t lp0 = (uint32_t)__bfloat16_as_ushort(l0) |
                               ((uint32_t)__bfloat16_as_ushort(l1) << 16);
                uint32_t lp1 = (uint32_t)__bfloat16_as_ushort(l2) |
                               ((uint32_t)__bfloat16_as_ushort(l3) << 16);
                *(uint32_t*)(Chi + (size_t)r * Ntot + cc) = hp0;
                *(uint32_t*)(Chi + (size_t)(r + 8) * Ntot + cc) = hp1;
                *(uint32_t*)(Clo + (size_t)r * Ntot + cc) = lp0;
                *(uint32_t*)(Clo + (size_t)(r + 8) * Ntot + cc) = lp1;
            } else {
                *(float2*)(Cf + (size_t)r * Ntot + cc) = make_float2(v0, v1);
                *(float2*)(Cf + (size_t)(r + 8) * Ntot + cc) = make_float2(v2, v3);
            }
        }
    }
}

// ---- LN + residual ----
__global__ __launch_bounds__(256) void ln_residual(const float* __restrict__ gam,
                                                   const float* __restrict__ bet) {
    __shared__ float red[40];
    int row = blockIdx.x, tid = threadIdx.x;
    const float* y = g_y + (size_t)row * DIM;
    float* h = g_h + (size_t)row * DIM;
    float xv[4], s = 0.0f;
    #pragma unroll
    for (int q = 0; q < 4; q++) { xv[q] = y[tid + q * 256]; s += xv[q]; }
    float mean = blockSum256(s, red, tid) * (1.0f / DIM);
    float vs = 0.0f;
    #pragma unroll
    for (int q = 0; q < 4; q++) { float d = xv[q] - mean; vs += d * d; }
    float var = blockSum256(vs, red, tid) * (1.0f / DIM);
    float rs = rsqrtf(var + 1e-5f);
    #pragma unroll
    for (int q = 0; q < 4; q++) {
        int d = tid + q * 256;
        h[d] += (xv[q] - mean) * rs * gam[d] + bet[d];
    }
}

// ---- post-pass: out[b][t] = LN(frall[t][b] + h[b][t]) ----
__global__ __launch_bounds__(256) void ln_out(const float* __restrict__ gam,
                                              const float* __restrict__ bet,
                                              float* __restrict__ out) {
    __shared__ float red[40];
    int row = blockIdx.x, tid = threadIdx.x;
    int b = row / TT, t = row % TT;
    const float* fr = g_frall + ((size_t)t * NBATCH + b) * DIM;
    const float* h = g_h + (size_t)row * DIM;
    float xv[4], s = 0.0f;
    #pragma unroll
    for (int q = 0; q < 4; q++) {
        int d = tid + q * 256;
        xv[q] = fr[d] + h[d];
        s += xv[q];
    }
    float mean = blockSum256(s, red, tid) * (1.0f / DIM);
    float vs = 0.0f;
    #pragma unroll
    for (int q = 0; q < 4; q++) { float dd = xv[q] - mean; vs += dd * dd; }
    float var = blockSum256(vs, red, tid) * (1.0f / DIM);
    float rs = rsqrtf(var + 1e-5f);
    float* o = out + (size_t)row * DIM;
    #pragma unroll
    for (int q = 0; q < 4; q++) {
        int d = tid + q * 256;
        o[d] = (xv[q] - mean) * rs * gam[d] + bet[d];
    }
}

// ---- persistent scan ----
__global__ __launch_bounds__(256) void scan_kernel(
    const unsigned char* __restrict__ mask,
    const float* __restrict__ memK, const float* __restrict__ fuseW,
    const float* __restrict__ mlng, const float* __restrict__ mlnb)
{
    extern __shared__ float sm[];
    float* Ks  = sm + SM_KS;
    float* Wf  = sm + SM_WF;
    float* xc  = sm + SM_XC;
    float* red = sm + SM_RED;
    unsigned long long* pred = (unsigned long long*)(sm + SM_RED);
    float* slng = sm + SM_LNG;
    float* slnb = sm + SM_LNB;
    int tid = threadIdx.x, cta = blockIdx.x;
    int wrp = tid >> 5, lan = tid & 31;

    {
        const float4* src = (const float4*)(memK + (size_t)cta * 16 * DIM);
        float4* dst = (float4*)Ks;
        for (int i = tid; i < 4096; i += 256) dst[i] = src[i];
    }
    {
        int c0 = cta * 8;
        float2* Wf2 = (float2*)Wf;
        for (int i = tid; i < 4096; i += 256) {
            int c2 = i >> 10, d = i & 1023;
            float2 v;
            v.x = fuseW[(size_t)(DIM + d) * DIM + c0 + 2 * c2];
            v.y = fuseW[(size_t)(DIM + d) * DIM + c0 + 2 * c2 + 1];
            Wf2[i] = v;
        }
    }
    for (int i = tid; i < 1024; i += 256) { slng[i] = mlng[i]; slnb[i] = mlnb[i]; }
    int kind = g_mask_kind;
    __syncthreads();

    float4 ph[8];
    #pragma unroll
    for (int k = 0; k < 8; k++) {
        int i = tid + k * 256; int b = i >> 8, d4 = i & 255;
        ph[k] = ((const float4*)(g_h + (size_t)(b * TT) * DIM))[d4];
    }

    for (int t = 0; t < TT; t++) {
        float cpre = g_cpre[t], cpost = g_cpost[t];
        int tgt = t + 1, p = t & 1;
        float* sc_p = g_scores + (size_t)p * SCO;
        float* sw_p = g_sw + (size_t)p * SWO;
        float* vt_p = g_vt + (size_t)p * NBATCH * DIM;
        float* fr_t = g_frall + (size_t)t * NBATCH * DIM;

        #pragma unroll
        for (int k = 0; k < 8; k++) {
            int i = tid + k * 256; int b = i >> 8, d4 = i & 255;
            ((float4*)(xc + b * 2048))[d4] = ph[k];
        }
        __syncthreads();

        // phase A
        {
            int hh = lan >> 3, r8 = lan & 7;
            int r0 = 2 * wrp, r1 = r0 + 1;
            float a0[8], a1[8];
            #pragma unroll
            for (int b = 0; b < 8; b++) { a0[b] = 0.0f; a1[b] = 0.0f; }
            const float* K0 = Ks + r0 * 1024 + hh * 256 + r8 * 4;
            const float* K1 = Ks + r1 * 1024 + hh * 256 + r8 * 4;
            const float* hb = xc + hh * 256 + r8 * 4;
            #pragma unroll
            for (int j = 0; j < 8; j++) {
                int off = j * 32;
                float4 k0 = *(const float4*)(K0 + off);
                float4 k1 = *(const float4*)(K1 + off);
                #pragma unroll
                for (int b = 0; b < 8; b++) {
                    float4 hv = *(const float4*)(hb + b * 2048 + off);
                    a0[b] += k0.x * hv.x + k0.y * hv.y + k0.z * hv.z + k0.w * hv.w;
                    a1[b] += k1.x * hv.x + k1.y * hv.y + k1.z * hv.z + k1.w * hv.w;
                }
            }
            #pragma unroll
            for (int o = 4; o; o >>= 1) {
                #pragma unroll
                for (int b = 0; b < 8; b++) {
                    a0[b] += __shfl_xor_sync(0xFFFFFFFFu, a0[b], o);
                    a1[b] += __shfl_xor_sync(0xFFFFFFFFu, a1[b], o);
                }
            }
            float t0[8], t1[8];
            #pragma unroll
            for (int b = 0; b < 8; b++) { t0[b] = a0[b]; t1[b] = a1[b]; }
            #pragma unroll
            for (int o = 8; o <= 16; o <<= 1) {
                #pragma unroll
                for (int b = 0; b < 8; b++) {
                    t0[b] += __shfl_xor_sync(0xFFFFFFFFu, t0[b], o);
                    t1[b] += __shfl_xor_sync(0xFFFFFFFFu, t1[b], o);
                }
            }
            int s0 = cta * 16 + r0, s1 = s0 + 1;
            if (r8 == 0) {
                #pragma unroll
                for (int b = 0; b < 8; b++) {
                    sc_p[(size_t)(b * NH + hh) * NS + s0] = a0[b] * INV_SQRT_DH;
                    sc_p[(size_t)(b * NH + hh) * NS + s1] = a1[b] * INV_SQRT_DH;
                }
            }
            if (lan == 0) {
                #pragma unroll
                for (int b = 0; b < 8; b++) {
                    sw_p[b * NS + s0] = t0[b] * INV_SQRT_D;
                    sw_p[b * NS + s1] = t1[b] * INV_SQRT_D;
                }
            }
        }
        __syncthreads();
        if (tid == 0) st_rel(&g_fscore[cta], tgt);

        // phase B
        if (cta < 32) {
            wait_n(g_fscore, NG, tgt, tid);
            int b = cta >> 2, h = cta & 3;
            const float* sc = sc_p + (size_t)(b * NH + h) * NS;
            float4 s0v = *(const float4*)(sc + tid * 8);
            float4 s1v = *(const float4*)(sc + tid * 8 + 4);
            unsigned long long P[8];
            P[0] = packkv(s0v.x, tid * 8 + 0); P[1] = packkv(s0v.y, tid * 8 + 1);
            P[2] = packkv(s0v.z, tid * 8 + 2); P[3] = packkv(s0v.w, tid * 8 + 3);
            P[4] = packkv(s1v.x, tid * 8 + 4); P[5] = packkv(s1v.y, tid * 8 + 5);
            P[6] = packkv(s1v.z, tid * 8 + 6); P[7] = packkv(s1v.w, tid * 8 + 7);
            psort8(P);
            pbfly(P, 1); pbfly(P, 2); pbfly(P, 4); pbfly(P, 8); pbfly(P, 16);
            if (lan == 0) {
                #pragma unroll
                for (int e = 0; e < 8; e++) pred[wrp * 8 + e] = P[e];
            }
            __syncthreads();
            if (wrp == 0) {
                unsigned long long Q[8];
                if (lan < 8) {
                    #pragma unroll
                    for (int e = 0; e < 8; e++) Q[e] = pred[lan * 8 + e];
                } else {
                    #pragma unroll
                    for (int e = 0; e < 8; e++) Q[e] = 0ull;
                }
                pbfly(Q, 1); pbfly(Q, 2); pbfly(Q, 4);
                if (lan == 0) {
                    #pragma unroll
                    for (int e = 0; e < 8; e++) pred[e] = Q[e];
                }
            }
            __syncthreads();
            float topv[NKTOP]; int topi[NKTOP];
            #pragma unroll
            for (int e = 0; e < 8; e++) {
                unsigned long long pe = pred[e];
                topv[e] = unpack_val(pe); topi[e] = unpack_idx(pe);
            }
            float w8[NKTOP], Z = 0.0f;
            #pragma unroll
            for (int k = 0; k < NKTOP; k++) { w8[k] = expf(topv[k] - topv[0]); Z += w8[k]; }
            float invZ = 1.0f / Z;
            float accv = 0.0f;
            #pragma unroll
            for (int k = 0; k < NKTOP; k++)
                accv += w8[k] * g_Vbuf[(size_t)topi[k] * DIM + h * NDh + tid];
            vt_p[b * DIM + h * NDh + tid] = accv * invZ * cpre;
            __syncthreads();
            if (tid == 0) st_rel(&g_fvt[cta], tgt);
        } else if (cta < 40) {
            wait_n(g_fscore, NG, tgt, tid);
            int b = cta - 32;
            const float* swp = sw_p + b * NS;
            float4 s0v = *(const float4*)(swp + tid * 8);
            float4 s1v = *(const float4*)(swp + tid * 8 + 4);
            float v[8] = {s0v.x, s0v.y, s0v.z, s0v.w, s1v.x, s1v.y, s1v.z, s1v.w};
            unsigned long long best = packkv(v[0], tid * 8);
            #pragma unroll
            for (int k = 1; k < 8; k++) {
                unsigned long long c = packkv(v[k], tid * 8 + k);
                if (c > best) best = c;
            }
            #pragma unroll
            for (int o = 16; o; o >>= 1) {
                unsigned long long c = __shfl_xor_sync(0xFFFFFFFFu, best, o);
                if (c > best) best = c;
            }
            if (lan == 0) pred[wrp] = best;
            __syncthreads();
            if (tid == 0) {
                unsigned long long m = pred[0];
                for (int k = 1; k < 8; k++) if (pred[k] > m) m = pred[k];
                pred[8] = m;
            }
            __syncthreads();
            unsigned long long m = pred[8];
            float mv = unpack_val(m);
            __syncthreads();
            float se = 0.0f;
            #pragma unroll
            for (int k = 0; k < 8; k++) se += expf(v[k] - mv);
            float Z = blockSum256(se, red, tid);
            if (tid == 0) {
                float surprise = 1.0f - 1.0f / Z;
                int midx = b * TT + t;
                float mk;
                if (kind == 0)      mk = ((const float*)mask)[midx];
                else if (kind == 1) mk = (float)((const int*)mask)[midx];
                else                mk = (float)mask[midx];
                float lr = (surprise > SURPRISE_TH ? LR_FAST : LR_DEEP);
                lr *= (mk != 0.0f ? 1.0f : 0.0f);
                g_slot[p][b] = unpack_idx(m);
                g_lr[p][b] = lr;
            }
            __syncthreads();
            if (tid == 0) st_rel(&g_fvt[cta], tgt);
        }

        wait_n(g_fvt, 40, tgt, tid);

        for (int i = tid; i < 2048; i += 256) {
            int b = i >> 8, d4 = i & 255;
            ((float4*)(xc + b * 2048 + 1024))[d4] =
                ((const float4*)(vt_p + b * DIM))[d4];
        }
        __syncthreads();

        // phase C (v-half; h-part precomputed in g_y)
        if (tid < 128) {
            int w = tid >> 5, l = tid & 31;
            int b0 = w * 2;
            const float2* Wf2 = (const float2*)Wf;
            float A0[8], A1[8];
            #pragma unroll
            for (int c = 0; c < 8; c++) { A0[c] = 0.0f; A1[c] = 0.0f; }
            for (int j = 0; j < 32; j++) {
                int d = j * 32 + l;
                float x0 = xc[b0 * 2048 + 1024 + d];
                float x1 = xc[(b0 + 1) * 2048 + 1024 + d];
                #pragma unroll
                for (int c2 = 0; c2 < 4; c2++) {
                    float2 wv = Wf2[c2 * 1024 + d];
                    A0[2 * c2]     += x0 * wv.x; A0[2 * c2 + 1] += x0 * wv.y;
                    A1[2 * c2]     += x1 * wv.x; A1[2 * c2 + 1] += x1 * wv.y;
                }
            }
            #pragma unroll
            for (int o = 16; o; o >>= 1) {
                #pragma unroll
                for (int c = 0; c < 8; c++) {
                    A0[c] += __shfl_xor_sync(0xFFFFFFFFu, A0[c], o);
                    A1[c] += __shfl_xor_sync(0xFFFFFFFFu, A1[c], o);
                }
            }
            if (l == 0) {
                int c0 = cta * 8;
                const float* fh0 = g_y + (size_t)(b0 * TT + t) * DIM + c0;
                const float* fh1 = g_y + (size_t)((b0 + 1) * TT + t) * DIM + c0;
                #pragma unroll
                for (int c = 0; c < 8; c++) {
                    fr_t[b0 * DIM + c0 + c] = A0[c] + fh0[c];
                    fr_t[(b0 + 1) * DIM + c0 + c] = A1[c] + fh1[c];
                }
            }
        }
        __syncthreads();
        if (tid == 0) st_rel(&g_ffused[cta], tgt);

        if (t + 1 < TT) {
            #pragma unroll
            for (int k = 0; k < 8; k++) {
                int i = tid + k * 256; int b = i >> 8, d4 = i & 255;
                ph[k] = ((const float4*)(g_h + (size_t)(b * TT + t + 1) * DIM))[d4];
            }
        }

        // phase E: only slot-owner CTAs take the full-grid wait
        bool is_owner = false;
        #pragma unroll
        for (int b = 0; b < 8; b++) if ((g_slot[p][b] >> 4) == cta) is_owner = true;
        if (is_owner) {
            wait_n(g_ffused, NG, tgt, tid);
            #pragma unroll 1
            for (int b = 0; b < 8; b++) {
                if ((g_slot[p][b] >> 4) != cta) continue;
                float xv[4], s = 0.0f;
                #pragma unroll
                for (int q = 0; q < 4; q++) {
                    int d = tid + q * 256;
                    xv[q] = fr_t[b * DIM + d] + xc[b * 2048 + d];
                    s += xv[q];
                }
                float mean = blockSum256(s, red, tid) * (1.0f / DIM);
                float vs = 0.0f;
                #pragma unroll
                for (int q = 0; q < 4; q++) { float dd = xv[q] - mean; vs += dd * dd; }
                float var = blockSum256(vs, red, tid) * (1.0f / DIM);
                if (tid == 0) { red[40 + b] = mean; red[48 + b] = rsqrtf(var + 1e-5f); }
            }
            __syncthreads();
            float invcp = 1.0f / cpost;
            #pragma unroll 1
            for (int r = 0; r < 16; r++) {
                int srow = cta * 16 + r;
                bool hit = false;
                #pragma unroll
                for (int b = 0; b < 8; b++) if (g_slot[p][b] == srow) hit = true;
                if (!hit) continue;
                #pragma unroll
                for (int q = 0; q < 4; q++) {
                    int d = tid + q * 256;
                    float kpre = Ks[r * 1024 + d];
                    float vpre = g_Vbuf[(size_t)srow * DIM + d];
                    float ka = 0.0f, va = 0.0f;
                    #pragma unroll
                    for (int b = 0; b < 8; b++) {
                        if (g_slot[p][b] == srow) {
                            float lr = g_lr[p][b];
                            float f = fr_t[b * DIM + d] + xc[b * 2048 + d];
                            float vw = (f - red[40 + b]) * red[48 + b] * slng[d] + slnb[d];
                            ka += lr * (xc[b * 2048 + d] - kpre);
                            va += lr * invcp * (vw - cpost * vpre);
                        }
                    }
                    Ks[r * 1024 + d] = kpre + ka;
                    g_Vbuf[(size_t)srow * DIM + d] = vpre + va;
                }
            }
        }
        __syncthreads();
    }
}

// ---- launch ----
extern "C" void kernel_launch(void* const* d_in, const int* in_sizes, int n_in,
                              void* d_out, int out_size) {
    const float* x      = (const float*)d_in[0];
    const unsigned char* mask = (const unsigned char*)d_in[1];
    const float* W1     = (const float*)d_in[2];
    const float* b1     = (const float*)d_in[3];
    const float* W2     = (const float*)d_in[4];
    const float* b2     = (const float*)d_in[5];
    const float* ln_g   = (const float*)d_in[6];
    const float* ln_b   = (const float*)d_in[7];
    const float* fuse_W = (const float*)d_in[8];
    const float* fuse_b = (const float*)d_in[9];
    const float* mln_g  = (const float*)d_in[10];
    const float* mln_b  = (const float*)d_in[11];
    const float* mem_K  = (const float*)d_in[12];
    const float* mem_V  = (const float*)d_in[13];
    float* out = (float*)d_out;

    float *p_h, *p_y, *p_V;
    __nv_bfloat16 *p_hhi, *p_hlo, *p_thi, *p_tlo, *p_w1h, *p_w1l, *p_w2h, *p_w2l;
    cudaGetSymbolAddress((void**)&p_h, g_h);
    cudaGetSymbolAddress((void**)&p_y, g_y);
    cudaGetSymbolAddress((void**)&p_V, g_Vbuf);
    cudaGetSymbolAddress((void**)&p_hhi, g_hhi);
    cudaGetSymbolAddress((void**)&p_hlo, g_hlo);
    cudaGetSymbolAddress((void**)&p_thi, g_thi);
    cudaGetSymbolAddress((void**)&p_tlo, g_tlo);
    cudaGetSymbolAddress((void**)&p_w1h, g_w1thi);
    cudaGetSymbolAddress((void**)&p_w1l, g_w1tlo);
    cudaGetSymbolAddress((void**)&p_w2h, g_w2thi);
    cudaGetSymbolAddress((void**)&p_w2l, g_w2tlo);

    cudaMemcpyAsync(p_h, x, (size_t)NBATCH * TT * DIM * 4, cudaMemcpyDeviceToDevice, 0);
    cudaMemcpyAsync(p_V, mem_V, (size_t)NS * DIM * 4, cudaMemcpyDeviceToDevice, 0);
    init_kernel<<<1, 512>>>(mask);

    cudaFuncSetAttribute(gemm_mma<1>, cudaFuncAttributeMaxDynamicSharedMemorySize, GEMM_SMEM_BYTES);
    cudaFuncSetAttribute(gemm_mma<0>, cudaFuncAttributeMaxDynamicSharedMemorySize, GEMM_SMEM_BYTES);

    const int M = NBATCH * TT;
    for (int i = 0; i < 2; i++) {
        conv_split<<<(M * DIM + 255) / 256, 256>>>(p_h, p_hhi, p_hlo, M * DIM);
        conv_T<<<dim3(2 * DIM / 32, DIM / 32), 256>>>(
            W1 + (size_t)i * DIM * 2 * DIM, p_w1h, p_w1l, DIM, 2 * DIM);
        gemm_mma<1><<<dim3(2 * DIM / BN, M / BM), 256, GEMM_SMEM_BYTES>>>(
            p_hhi, p_hlo, p_w1h, p_w1l, b1 + (size_t)i * 2 * DIM,
            nullptr, p_thi, p_tlo, DIM, 2 * DIM);
        conv_T<<<dim3(DIM / 32, 2 * DIM / 32), 256>>>(
            W2 + (size_t)i * 2 * DIM * DIM, p_w2h, p_w2l, 2 * DIM, DIM);
        gemm_mma<0><<<dim3(DIM / BN, M / BM), 256, GEMM_SMEM_BYTES>>>(
            p_thi, p_tlo, p_w2h, p_w2l, b2 + (size_t)i * DIM,
            p_y, nullptr, nullptr, 2 * DIM, DIM);
        ln_residual<<<M, 256>>>(ln_g + (size_t)i * DIM, ln_b + (size_t)i * DIM);
    }

    // fused_h = h @ fuse_W[0:1024] + fuse_b  (into g_y)
    conv_split<<<(M * DIM + 255) / 256, 256>>>(p_h, p_hhi, p_hlo, M * DIM);
    conv_T<<<dim3(DIM / 32, DIM / 32), 256>>>(fuse_W, p_w1h, p_w1l, DIM, DIM);
    gemm_mma<0><<<dim3(DIM / BN, M / BM), 256, GEMM_SMEM_BYTES>>>(
        p_hhi, p_hlo, p_w1h, p_w1l, fuse_b, p_y, nullptr, nullptr, DIM, DIM);

    cudaFuncSetAttribute(scan_kernel, cudaFuncAttributeMaxDynamicSharedMemorySize, SMEM_BYTES);
    scan_kernel<<<NG, 256, SMEM_BYTES>>>(mask, mem_K, fuse_W, mln_g, mln_b);

    ln_out<<<M, 256>>>(mln_g, mln_b, out);
}